// round 13
// baseline (speedup 1.0000x reference)
#include <cuda_runtime.h>
#include <math.h>
#include <stdint.h>

#define NN 50000
#define EE 800000
#define DD 64
#define KK 3
#define NKMAX (NN * KK)
#define AGG_EPS 1e-6f
#define BN_EPS  1e-5f
#define SCAN_BLK 1024
#define MAXBLKS 256

// GEMM (tensor core) tiling
#define GR 128               // rows per block
#define XS 72                // stride (mod 32 == 8): A banks 8*gid+tig (2-way), B banks 8*tig+gid (free)
#define GEMM_SMEM ((GR * XS + DD * XS) * 4)   // 55296 B

// Scratch (device globals — no allocation allowed)
__device__ float g_Dx[NN * DD];
__device__ float g_Bx[KK * NN * DD];
__device__ float g_xnew[NN * DD];     // gemm writes Ax; agg overwrites with x_new
__device__ float g_fsum[DD];
__device__ float g_fsq[DD];

__device__ int g_count[NKMAX];
__device__ int g_partial[NKMAX];
__device__ int g_blocksum[MAXBLKS];
__device__ int g_segstart[NKMAX + 1];
__device__ int g_cursor[NKMAX];
__device__ int g_sorted[EE];

__device__ __forceinline__ float tanh_fast(float x) {
    float y;
    asm("tanh.approx.f32 %0, %1;" : "=f"(y) : "f"(x));
    return y;
}
__device__ __forceinline__ float sigmoid_fast(float x) {
    return fmaf(tanh_fast(0.5f * x), 0.5f, 0.5f);
}
__device__ __forceinline__ float tf32_rna(float x) {
    float y;
    asm("cvt.rna.tf32.f32 %0, %1;" : "=f"(y) : "f"(x));
    return y;
}

// ---------------------------------------------------------------------------
// K0: zero histogram + BN accumulators
// ---------------------------------------------------------------------------
__global__ void zero_kernel(int NK) {
    int idx = blockIdx.x * blockDim.x + threadIdx.x;
    int stride = gridDim.x * blockDim.x;
    for (int i = idx; i < NK; i += stride) g_count[i] = 0;
    if (idx < DD) { g_fsum[idx] = 0.f; g_fsq[idx] = 0.f; }
}

// ---------------------------------------------------------------------------
// K1: histogram of edges per segment (seg = i*K + ke)
// ---------------------------------------------------------------------------
__global__ void hist_kernel(const int* __restrict__ ei, const int* __restrict__ ea, int E) {
    int e = blockIdx.x * blockDim.x + threadIdx.x;
    if (e >= E) return;
    int i  = ei[E + e];
    int ke = ea[e] - 1;
    atomicAdd(&g_count[i * KK + ke], 1);
}

// ---------------------------------------------------------------------------
// K2a: per-block exclusive scan (shfl-based)
// ---------------------------------------------------------------------------
__global__ void scan1_kernel(int NK) {
    __shared__ int warpsum[32];
    int t = threadIdx.x;
    int lane = t & 31;
    int w = t >> 5;
    int idx = blockIdx.x * SCAN_BLK + t;
    int v = (idx < NK) ? g_count[idx] : 0;

    int x = v;
    #pragma unroll
    for (int off = 1; off < 32; off <<= 1) {
        int y = __shfl_up_sync(0xffffffff, x, off);
        if (lane >= off) x += y;
    }
    if (lane == 31) warpsum[w] = x;
    __syncthreads();
    if (w == 0) {
        int s = (lane < SCAN_BLK / 32) ? warpsum[lane] : 0;
        #pragma unroll
        for (int off = 1; off < 32; off <<= 1) {
            int y = __shfl_up_sync(0xffffffff, s, off);
            if (lane >= off) s += y;
        }
        if (lane < SCAN_BLK / 32) warpsum[lane] = s;
    }
    __syncthreads();
    int wpre = (w > 0) ? warpsum[w - 1] : 0;
    int incl = x + wpre;
    if (idx < NK) g_partial[idx] = incl - v;
    if (t == SCAN_BLK - 1) g_blocksum[blockIdx.x] = incl;
}

// K2b: fused block-offset scan + apply
__global__ void scan23_kernel(int NK, int E, int nblocks) {
    __shared__ int boff[MAXBLKS];
    int t = threadIdx.x;
    if (t < 32) {
        int acc = 0;
        for (int base = 0; base < nblocks; base += 32) {
            int idx = base + t;
            int v = (idx < nblocks) ? g_blocksum[idx] : 0;
            int x = v;
            #pragma unroll
            for (int off = 1; off < 32; off <<= 1) {
                int y = __shfl_up_sync(0xffffffff, x, off);
                if (t >= off) x += y;
            }
            if (idx < nblocks) boff[idx] = acc + x - v;
            acc += __shfl_sync(0xffffffff, x, 31);
        }
    }
    __syncthreads();
    int idx = blockIdx.x * blockDim.x + t;
    if (idx < NK) {
        int v = g_partial[idx] + boff[idx >> 10];
        g_segstart[idx] = v;
        g_cursor[idx] = v;
    }
    if (idx == 0) g_segstart[NK] = E;
}

// ---------------------------------------------------------------------------
// K3: scatter source node ids into sorted order
// ---------------------------------------------------------------------------
__global__ void scatter_kernel(const int* __restrict__ ei, const int* __restrict__ ea, int E) {
    int e = blockIdx.x * blockDim.x + threadIdx.x;
    if (e >= E) return;
    int j  = ei[e];
    int i  = ei[E + e];
    int ke = ea[e] - 1;
    int pos = atomicAdd(&g_cursor[i * KK + ke], 1);
    g_sorted[pos] = j;
}

// ---------------------------------------------------------------------------
// GEMM compute core: one 128x64 tile via TF32 mma.sync.m16n8k8.
// ---------------------------------------------------------------------------
__device__ __forceinline__ void mma_tile(const float* __restrict__ Xs,
                                         const float* __restrict__ Ws,
                                         const float* __restrict__ b,
                                         float* __restrict__ dst,
                                         int row0, int N, int t) {
    int w    = t >> 5;
    int lane = t & 31;
    int gid  = lane >> 2;
    int tig  = lane & 3;
    int r0   = w * 16;

    float c[8][4];
    #pragma unroll
    for (int nt = 0; nt < 8; nt++)
        #pragma unroll
        for (int q = 0; q < 4; q++) c[nt][q] = 0.f;

    const float* Arow1 = Xs + (r0 + gid) * XS + tig;
    const float* Arow2 = Xs + (r0 + gid + 8) * XS + tig;
    const float* Brow  = Ws + tig * XS + gid;

    #pragma unroll
    for (int ks = 0; ks < 8; ks++) {
        int k0 = ks * 8;
        uint32_t a0 = __float_as_uint(Arow1[k0]);
        uint32_t a1 = __float_as_uint(Arow2[k0]);
        uint32_t a2 = __float_as_uint(Arow1[k0 + 4]);
        uint32_t a3 = __float_as_uint(Arow2[k0 + 4]);

        const float* B0 = Brow + k0 * XS;
        #pragma unroll
        for (int nt = 0; nt < 8; nt++) {
            uint32_t b0 = __float_as_uint(B0[nt * 8]);
            uint32_t b1 = __float_as_uint(B0[4 * XS + nt * 8]);
            asm volatile(
                "mma.sync.aligned.m16n8k8.row.col.f32.tf32.tf32.f32 "
                "{%0,%1,%2,%3}, {%4,%5,%6,%7}, {%8,%9}, {%0,%1,%2,%3};"
                : "+f"(c[nt][0]), "+f"(c[nt][1]), "+f"(c[nt][2]), "+f"(c[nt][3])
                : "r"(a0), "r"(a1), "r"(a2), "r"(a3), "r"(b0), "r"(b1));
        }
    }

    int gr1 = row0 + r0 + gid;
    int gr2 = gr1 + 8;
    #pragma unroll
    for (int nt = 0; nt < 8; nt++) {
        int col = nt * 8 + tig * 2;
        float bx = b[col], by = b[col + 1];
        if (gr1 < N) {
            float2 o; o.x = c[nt][0] + bx; o.y = c[nt][1] + by;
            *(float2*)&dst[(size_t)gr1 * DD + col] = o;
        }
        if (gr2 < N) {
            float2 o; o.x = c[nt][2] + bx; o.y = c[nt][3] + by;
            *(float2*)&dst[(size_t)gr2 * DD + col] = o;
        }
    }
}

__device__ __forceinline__ void stage_W(float* Ws, const float* __restrict__ W, int t) {
    for (int i = t; i < DD * (DD / 4); i += 256) {
        int k  = i >> 4;
        int n4 = (i & 15) << 2;
        float4 v = *(const float4*)&W[k * DD + n4];
        v.x = tf32_rna(v.x); v.y = tf32_rna(v.y);
        v.z = tf32_rna(v.z); v.w = tf32_rna(v.w);
        *(float4*)&Ws[k * XS + n4] = v;
    }
}

// ---------------------------------------------------------------------------
// K4: four blocks-y: y=0 computes BOTH Ax and Dx from one staging of xs[2]
// (two W passes through the same SMEM buffer); y=1..3 compute Bx[y-1].
// ---------------------------------------------------------------------------
__global__ __launch_bounds__(256) void gemm_kernel(
        const float* __restrict__ xs,
        const float* __restrict__ Wa, const float* __restrict__ ba,
        const float* __restrict__ Wd, const float* __restrict__ bd,
        const float* __restrict__ Wb, const float* __restrict__ bb,
        int N) {
    extern __shared__ float smem[];
    float* Xs = smem;               // [GR][XS]
    float* Ws = smem + GR * XS;     // [DD][XS], row-major W[k][n]

    int m = blockIdx.y;             // 0: Ax+Dx, 1..3: Bx[m-1]
    const float* X;
    if (m == 0) X = xs + 2 * (size_t)N * DD;
    else        X = xs + (size_t)(2 - (m - 1)) * N * DD;

    int t = threadIdx.x;
    int row0 = blockIdx.x * GR;

    // Stage X, vectorized (tf32-rounded)
    for (int i = t; i < GR * (DD / 4); i += 256) {
        int r  = i >> 4;
        int c4 = (i & 15) << 2;
        int gr = row0 + r;
        float4 v = make_float4(0.f, 0.f, 0.f, 0.f);
        if (gr < N) v = *(const float4*)&X[(size_t)gr * DD + c4];
        v.x = tf32_rna(v.x); v.y = tf32_rna(v.y);
        v.z = tf32_rna(v.z); v.w = tf32_rna(v.w);
        *(float4*)&Xs[r * XS + c4] = v;
    }

    if (m == 0) {
        stage_W(Ws, Wa, t);
        __syncthreads();
        mma_tile(Xs, Ws, ba, g_xnew, row0, N, t);
        __syncthreads();                 // all Ws reads done before restage
        stage_W(Ws, Wd, t);
        __syncthreads();
        mma_tile(Xs, Ws, bd, g_Dx, row0, N, t);
    } else {
        int k = m - 1;
        stage_W(Ws, Wb + (size_t)k * DD * DD, t);
        __syncthreads();
        mma_tile(Xs, Ws, bb + k * DD, g_Bx + (size_t)k * N * DD, row0, N, t);
    }
}

// ---------------------------------------------------------------------------
// K5: agg v7 — one warp per node, lane owns 2 dims. Edges processed as ONE
// contiguous flat stream [s0,s3) (the 3 k-segments are adjacent in g_sorted);
// hop-k derived from warp-uniform flat position (2 compares). Common case:
// quad entirely within one k -> uniform branch, 4 MLP gathers, partial sums
// merged into one of 3 register banks. Mixed quads (<=2/node) take a scalar
// path. BN stats fused.
// ---------------------------------------------------------------------------
__global__ __launch_bounds__(256) void agg_kernel(int N) {
    __shared__ float ssum[DD];
    __shared__ float ssq[DD];
    int t = threadIdx.x;
    if (t < DD) { ssum[t] = 0.f; ssq[t] = 0.f; }
    __syncthreads();

    int warp = (blockIdx.x * blockDim.x + t) >> 5;
    int lane = t & 31;

    if (warp < N) {
        int n = warp;
        int sv = 0;
        if (lane < 4) sv = __ldg(&g_segstart[3 * n + lane]);
        int s0 = __shfl_sync(0xffffffff, sv, 0);
        int b1 = __shfl_sync(0xffffffff, sv, 1);
        int b2 = __shfl_sync(0xffffffff, sv, 2);
        int s3 = __shfl_sync(0xffffffff, sv, 3);

        float2 d = *(const float2*)&g_Dx[(size_t)n * DD + lane * 2];
        const size_t ND = (size_t)N * DD;
        const float* B0 = g_Bx + lane * 2;

        float n0x = 0.f, n0y = 0.f, d0x = 0.f, d0y = 0.f;
        float n1x = 0.f, n1y = 0.f, d1x = 0.f, d1y = 0.f;
        float n2x = 0.f, n2y = 0.f, d2x = 0.f, d2y = 0.f;

        int total = s3 - s0;
        for (int base = 0; base < total; base += 32) {
            int li = s0 + base + lane;
            int jv = (li < s3) ? __ldg(&g_sorted[li]) : 0;
            int cnt = min(32, total - base);
            int q = 0;
            for (; q + 4 <= cnt; q += 4) {
                int e0 = s0 + base + q;
                int ka = (e0 >= b2) ? 2 : ((e0 >= b1) ? 1 : 0);
                int kb = (e0 + 3 >= b2) ? 2 : ((e0 + 3 >= b1) ? 1 : 0);
                int j0 = __shfl_sync(0xffffffff, jv, q);
                int j1 = __shfl_sync(0xffffffff, jv, q + 1);
                int j2 = __shfl_sync(0xffffffff, jv, q + 2);
                int j3 = __shfl_sync(0xffffffff, jv, q + 3);
                if (ka == kb) {
                    const float* Bk = B0 + (size_t)ka * ND;
                    float2 v0 = *(const float2*)(Bk + ((size_t)j0 << 6));
                    float2 v1 = *(const float2*)(Bk + ((size_t)j1 << 6));
                    float2 v2 = *(const float2*)(Bk + ((size_t)j2 << 6));
                    float2 v3 = *(const float2*)(Bk + ((size_t)j3 << 6));
                    float pnx = 0.f, pny = 0.f, pdx = 0.f, pdy = 0.f;
                    float sa, sb;
                    sa = sigmoid_fast(d.x + v0.x); sb = sigmoid_fast(d.y + v0.y);
                    pnx += sa * v0.x; pdx += sa; pny += sb * v0.y; pdy += sb;
                    sa = sigmoid_fast(d.x + v1.x); sb = sigmoid_fast(d.y + v1.y);
                    pnx += sa * v1.x; pdx += sa; pny += sb * v1.y; pdy += sb;
                    sa = sigmoid_fast(d.x + v2.x); sb = sigmoid_fast(d.y + v2.y);
                    pnx += sa * v2.x; pdx += sa; pny += sb * v2.y; pdy += sb;
                    sa = sigmoid_fast(d.x + v3.x); sb = sigmoid_fast(d.y + v3.y);
                    pnx += sa * v3.x; pdx += sa; pny += sb * v3.y; pdy += sb;
                    if (ka == 0)      { n0x += pnx; n0y += pny; d0x += pdx; d0y += pdy; }
                    else if (ka == 1) { n1x += pnx; n1y += pny; d1x += pdx; d1y += pdy; }
                    else              { n2x += pnx; n2y += pny; d2x += pdx; d2y += pdy; }
                } else {
                    #pragma unroll
                    for (int u = 0; u < 4; u++) {
                        int e = e0 + u;
                        int j = (u == 0) ? j0 : (u == 1) ? j1 : (u == 2) ? j2 : j3;
                        int k = (e >= b2) ? 2 : ((e >= b1) ? 1 : 0);
                        const float* Bk = B0 + (size_t)k * ND;
                        float2 v = *(const float2*)(Bk + ((size_t)j << 6));
                        float sa = sigmoid_fast(d.x + v.x);
                        float sb = sigmoid_fast(d.y + v.y);
                        if (k == 0)      { n0x += sa * v.x; d0x += sa; n0y += sb * v.y; d0y += sb; }
                        else if (k == 1) { n1x += sa * v.x; d1x += sa; n1y += sb * v.y; d1y += sb; }
                        else             { n2x += sa * v.x; d2x += sa; n2y += sb * v.y; d2y += sb; }
                    }
                }
            }
            for (; q < cnt; q++) {
                int e = s0 + base + q;
                int j = __shfl_sync(0xffffffff, jv, q);
                int k = (e >= b2) ? 2 : ((e >= b1) ? 1 : 0);
                const float* Bk = B0 + (size_t)k * ND;
                float2 v = *(const float2*)(Bk + ((size_t)j << 6));
                float sa = sigmoid_fast(d.x + v.x);
                float sb = sigmoid_fast(d.y + v.y);
                if (k == 0)      { n0x += sa * v.x; d0x += sa; n0y += sb * v.y; d0y += sb; }
                else if (k == 1) { n1x += sa * v.x; d1x += sa; n1y += sb * v.y; d1y += sb; }
                else             { n2x += sa * v.x; d2x += sa; n2y += sb * v.y; d2y += sb; }
            }
        }

        float eta0 = __fdividef(n0x, d0x + AGG_EPS) + __fdividef(n1x, d1x + AGG_EPS)
                   + __fdividef(n2x, d2x + AGG_EPS);
        float eta1 = __fdividef(n0y, d0y + AGG_EPS) + __fdividef(n1y, d1y + AGG_EPS)
                   + __fdividef(n2y, d2y + AGG_EPS);

        size_t obase = (size_t)n * DD + lane * 2;
        float2 a = *(const float2*)&g_xnew[obase];   // Ax
        float v0 = a.x + eta0 * (1.f / KK);
        float v1 = a.y + eta1 * (1.f / KK);
        float2 vo; vo.x = v0; vo.y = v1;
        *(float2*)&g_xnew[obase] = vo;

        atomicAdd(&ssum[lane * 2 + 0], v0);
        atomicAdd(&ssum[lane * 2 + 1], v1);
        atomicAdd(&ssq[lane * 2 + 0], v0 * v0);
        atomicAdd(&ssq[lane * 2 + 1], v1 * v1);
    }
    __syncthreads();
    if (t < DD) {
        atomicAdd(&g_fsum[t], ssum[t]);
        atomicAdd(&g_fsq[t],  ssq[t]);
    }
}

// ---------------------------------------------------------------------------
// K6: BatchNorm + ReLU (vectorized)
// ---------------------------------------------------------------------------
__global__ void bn_kernel(const float* __restrict__ gamma,
                          const float* __restrict__ beta,
                          float* __restrict__ out, int N) {
    int idx = blockIdx.x * blockDim.x + threadIdx.x;   // float4 index
    if (idx >= N * (DD / 4)) return;
    int d4 = (idx & 15) * 4;
    float invN = 1.f / (float)N;
    float4 x = *(const float4*)&g_xnew[(size_t)idx * 4];
    float4 o;
    #pragma unroll
    for (int i = 0; i < 4; i++) {
        int d = d4 + i;
        float mean = g_fsum[d] * invN;
        float var  = g_fsq[d] * invN - mean * mean;
        float xi = (i == 0) ? x.x : (i == 1) ? x.y : (i == 2) ? x.z : x.w;
        float y = gamma[d] * (xi - mean) * rsqrtf(var + BN_EPS) + beta[d];
        y = fmaxf(y, 0.f);
        if (i == 0) o.x = y; else if (i == 1) o.y = y; else if (i == 2) o.z = y; else o.w = y;
    }
    *(float4*)&out[(size_t)idx * 4] = o;
}

// ---------------------------------------------------------------------------
extern "C" void kernel_launch(void* const* d_in, const int* in_sizes, int n_in,
                              void* d_out, int out_size) {
    const float* xs    = (const float*)d_in[0];
    const int*   ei    = (const int*)d_in[1];
    const int*   ea    = (const int*)d_in[2];
    const float* Wa    = (const float*)d_in[3];
    const float* ba    = (const float*)d_in[4];
    const float* Wd    = (const float*)d_in[5];
    const float* bd    = (const float*)d_in[6];
    const float* Wb    = (const float*)d_in[7];
    const float* bb    = (const float*)d_in[8];
    const float* gamma = (const float*)d_in[9];
    const float* beta  = (const float*)d_in[10];
    float* out = (float*)d_out;

    int N = in_sizes[0] / (3 * DD);
    int E = in_sizes[2];
    int NK = N * KK;
    int nScanBlks = (NK + SCAN_BLK - 1) / SCAN_BLK;

    static cudaStream_t side = nullptr;
    static cudaEvent_t evFork = nullptr, evJoin = nullptr;
    static bool attrSet = false;
    if (!side) {
        cudaStreamCreateWithFlags(&side, cudaStreamNonBlocking);
        cudaEventCreateWithFlags(&evFork, cudaEventDisableTiming);
        cudaEventCreateWithFlags(&evJoin, cudaEventDisableTiming);
    }
    if (!attrSet) {
        cudaFuncSetAttribute(gemm_kernel,
                             cudaFuncAttributeMaxDynamicSharedMemorySize, GEMM_SMEM);
        attrSet = true;
    }

    cudaEventRecord(evFork, 0);
    cudaStreamWaitEvent(side, evFork, 0);

    zero_kernel<<<256, 256, 0, side>>>(NK);                       // #1
    hist_kernel<<<(E + 255) / 256, 256, 0, side>>>(ei, ea, E);    // #2
    scan1_kernel<<<nScanBlks, SCAN_BLK, 0, side>>>(NK);           // #3

    dim3 gGemm((N + GR - 1) / GR, 4);
    gemm_kernel<<<gGemm, 256, GEMM_SMEM>>>(xs, Wa, ba, Wd, bd, Wb, bb, N);  // #4 (profiled)

    scan23_kernel<<<(NK + 255) / 256, 256, 0, side>>>(NK, E, nScanBlks);    // #5
    scatter_kernel<<<(E + 255) / 256, 256, 0, side>>>(ei, ea, E);           // #6

    cudaEventRecord(evJoin, side);
    cudaStreamWaitEvent(0, evJoin, 0);

    agg_kernel<<<(N * 32 + 255) / 256, 256>>>(N);                 // #7

    bn_kernel<<<(N * (DD / 4) + 255) / 256, 256>>>(gamma, beta, out, N);    // #8
}

// round 14
// speedup vs baseline: 1.1283x; 1.1283x over previous
#include <cuda_runtime.h>
#include <math.h>
#include <stdint.h>

#define NN 50000
#define EE 800000
#define DD 64
#define KK 3
#define NKMAX (NN * KK)
#define AGG_EPS 1e-6f
#define BN_EPS  1e-5f
#define SCAN_BLK 1024
#define MAXBLKS 256

// GEMM (tensor core) tiling
#define GR 128               // rows per block
#define XS 72                // stride (mod 32 == 8)
#define GEMM_SMEM ((GR * XS + DD * XS) * 4)   // 55296 B

// Scratch (device globals — no allocation allowed)
__device__ float g_Dx[NN * DD];
__device__ float g_Bx[KK * NN * DD];
__device__ float g_xnew[NN * DD];     // gemm writes Ax; agg overwrites with x_new
__device__ float g_fsum[DD];
__device__ float g_fsq[DD];

__device__ int g_count[NKMAX];
__device__ int g_partial[NKMAX];
__device__ int g_blocksum[MAXBLKS];
__device__ int g_segstart[NKMAX + 1];
__device__ int g_cursor[NKMAX];
__device__ int g_sorted[EE];

__device__ __forceinline__ float tanh_fast(float x) {
    float y;
    asm("tanh.approx.f32 %0, %1;" : "=f"(y) : "f"(x));
    return y;
}
__device__ __forceinline__ float sigmoid_fast(float x) {
    return fmaf(tanh_fast(0.5f * x), 0.5f, 0.5f);
}
__device__ __forceinline__ float tf32_rna(float x) {
    float y;
    asm("cvt.rna.tf32.f32 %0, %1;" : "=f"(y) : "f"(x));
    return y;
}

// ---------------------------------------------------------------------------
// K0: zero histogram + BN accumulators
// ---------------------------------------------------------------------------
__global__ void zero_kernel(int NK) {
    int idx = blockIdx.x * blockDim.x + threadIdx.x;
    int stride = gridDim.x * blockDim.x;
    for (int i = idx; i < NK; i += stride) g_count[i] = 0;
    if (idx < DD) { g_fsum[idx] = 0.f; g_fsq[idx] = 0.f; }
}

// ---------------------------------------------------------------------------
// K1: histogram of edges per segment (seg = i*K + ke)
// ---------------------------------------------------------------------------
__global__ void hist_kernel(const int* __restrict__ ei, const int* __restrict__ ea, int E) {
    int e = blockIdx.x * blockDim.x + threadIdx.x;
    if (e >= E) return;
    int i  = ei[E + e];
    int ke = ea[e] - 1;
    atomicAdd(&g_count[i * KK + ke], 1);
}

// ---------------------------------------------------------------------------
// K2a: per-block exclusive scan (shfl-based)
// ---------------------------------------------------------------------------
__global__ void scan1_kernel(int NK) {
    __shared__ int warpsum[32];
    int t = threadIdx.x;
    int lane = t & 31;
    int w = t >> 5;
    int idx = blockIdx.x * SCAN_BLK + t;
    int v = (idx < NK) ? g_count[idx] : 0;

    int x = v;
    #pragma unroll
    for (int off = 1; off < 32; off <<= 1) {
        int y = __shfl_up_sync(0xffffffff, x, off);
        if (lane >= off) x += y;
    }
    if (lane == 31) warpsum[w] = x;
    __syncthreads();
    if (w == 0) {
        int s = (lane < SCAN_BLK / 32) ? warpsum[lane] : 0;
        #pragma unroll
        for (int off = 1; off < 32; off <<= 1) {
            int y = __shfl_up_sync(0xffffffff, s, off);
            if (lane >= off) s += y;
        }
        if (lane < SCAN_BLK / 32) warpsum[lane] = s;
    }
    __syncthreads();
    int wpre = (w > 0) ? warpsum[w - 1] : 0;
    int incl = x + wpre;
    if (idx < NK) g_partial[idx] = incl - v;
    if (t == SCAN_BLK - 1) g_blocksum[blockIdx.x] = incl;
}

// K2b: fused block-offset scan + apply
__global__ void scan23_kernel(int NK, int E, int nblocks) {
    __shared__ int boff[MAXBLKS];
    int t = threadIdx.x;
    if (t < 32) {
        int acc = 0;
        for (int base = 0; base < nblocks; base += 32) {
            int idx = base + t;
            int v = (idx < nblocks) ? g_blocksum[idx] : 0;
            int x = v;
            #pragma unroll
            for (int off = 1; off < 32; off <<= 1) {
                int y = __shfl_up_sync(0xffffffff, x, off);
                if (t >= off) x += y;
            }
            if (idx < nblocks) boff[idx] = acc + x - v;
            acc += __shfl_sync(0xffffffff, x, 31);
        }
    }
    __syncthreads();
    int idx = blockIdx.x * blockDim.x + t;
    if (idx < NK) {
        int v = g_partial[idx] + boff[idx >> 10];
        g_segstart[idx] = v;
        g_cursor[idx] = v;
    }
    if (idx == 0) g_segstart[NK] = E;
}

// ---------------------------------------------------------------------------
// K3: scatter source node ids into sorted order
// ---------------------------------------------------------------------------
__global__ void scatter_kernel(const int* __restrict__ ei, const int* __restrict__ ea, int E) {
    int e = blockIdx.x * blockDim.x + threadIdx.x;
    if (e >= E) return;
    int j  = ei[e];
    int i  = ei[E + e];
    int ke = ea[e] - 1;
    int pos = atomicAdd(&g_cursor[i * KK + ke], 1);
    g_sorted[pos] = j;
}

// ---------------------------------------------------------------------------
// GEMM compute core: one 128x64 tile via TF32 mma.sync.m16n8k8.
// ---------------------------------------------------------------------------
__device__ __forceinline__ void mma_tile(const float* __restrict__ Xs,
                                         const float* __restrict__ Ws,
                                         const float* __restrict__ b,
                                         float* __restrict__ dst,
                                         int row0, int N, int t) {
    int w    = t >> 5;
    int lane = t & 31;
    int gid  = lane >> 2;
    int tig  = lane & 3;
    int r0   = w * 16;

    float c[8][4];
    #pragma unroll
    for (int nt = 0; nt < 8; nt++)
        #pragma unroll
        for (int q = 0; q < 4; q++) c[nt][q] = 0.f;

    const float* Arow1 = Xs + (r0 + gid) * XS + tig;
    const float* Arow2 = Xs + (r0 + gid + 8) * XS + tig;
    const float* Brow  = Ws + tig * XS + gid;

    #pragma unroll
    for (int ks = 0; ks < 8; ks++) {
        int k0 = ks * 8;
        uint32_t a0 = __float_as_uint(Arow1[k0]);
        uint32_t a1 = __float_as_uint(Arow2[k0]);
        uint32_t a2 = __float_as_uint(Arow1[k0 + 4]);
        uint32_t a3 = __float_as_uint(Arow2[k0 + 4]);

        const float* B0 = Brow + k0 * XS;
        #pragma unroll
        for (int nt = 0; nt < 8; nt++) {
            uint32_t b0 = __float_as_uint(B0[nt * 8]);
            uint32_t b1 = __float_as_uint(B0[4 * XS + nt * 8]);
            asm volatile(
                "mma.sync.aligned.m16n8k8.row.col.f32.tf32.tf32.f32 "
                "{%0,%1,%2,%3}, {%4,%5,%6,%7}, {%8,%9}, {%0,%1,%2,%3};"
                : "+f"(c[nt][0]), "+f"(c[nt][1]), "+f"(c[nt][2]), "+f"(c[nt][3])
                : "r"(a0), "r"(a1), "r"(a2), "r"(a3), "r"(b0), "r"(b1));
        }
    }

    int gr1 = row0 + r0 + gid;
    int gr2 = gr1 + 8;
    #pragma unroll
    for (int nt = 0; nt < 8; nt++) {
        int col = nt * 8 + tig * 2;
        float bx = b[col], by = b[col + 1];
        if (gr1 < N) {
            float2 o; o.x = c[nt][0] + bx; o.y = c[nt][1] + by;
            *(float2*)&dst[(size_t)gr1 * DD + col] = o;
        }
        if (gr2 < N) {
            float2 o; o.x = c[nt][2] + bx; o.y = c[nt][3] + by;
            *(float2*)&dst[(size_t)gr2 * DD + col] = o;
        }
    }
}

__device__ __forceinline__ void stage_W(float* Ws, const float* __restrict__ W, int t) {
    for (int i = t; i < DD * (DD / 4); i += 256) {
        int k  = i >> 4;
        int n4 = (i & 15) << 2;
        float4 v = *(const float4*)&W[k * DD + n4];
        v.x = tf32_rna(v.x); v.y = tf32_rna(v.y);
        v.z = tf32_rna(v.z); v.w = tf32_rna(v.w);
        *(float4*)&Ws[k * XS + n4] = v;
    }
}

// ---------------------------------------------------------------------------
// K4: y=0 computes BOTH Ax and Dx from one staging of xs[2] (two W passes);
// y=1..3 compute Bx[y-1].
// ---------------------------------------------------------------------------
__global__ __launch_bounds__(256) void gemm_kernel(
        const float* __restrict__ xs,
        const float* __restrict__ Wa, const float* __restrict__ ba,
        const float* __restrict__ Wd, const float* __restrict__ bd,
        const float* __restrict__ Wb, const float* __restrict__ bb,
        int N) {
    extern __shared__ float smem[];
    float* Xs = smem;               // [GR][XS]
    float* Ws = smem + GR * XS;     // [DD][XS], row-major W[k][n]

    int m = blockIdx.y;             // 0: Ax+Dx, 1..3: Bx[m-1]
    const float* X;
    if (m == 0) X = xs + 2 * (size_t)N * DD;
    else        X = xs + (size_t)(2 - (m - 1)) * N * DD;

    int t = threadIdx.x;
    int row0 = blockIdx.x * GR;

    for (int i = t; i < GR * (DD / 4); i += 256) {
        int r  = i >> 4;
        int c4 = (i & 15) << 2;
        int gr = row0 + r;
        float4 v = make_float4(0.f, 0.f, 0.f, 0.f);
        if (gr < N) v = *(const float4*)&X[(size_t)gr * DD + c4];
        v.x = tf32_rna(v.x); v.y = tf32_rna(v.y);
        v.z = tf32_rna(v.z); v.w = tf32_rna(v.w);
        *(float4*)&Xs[r * XS + c4] = v;
    }

    if (m == 0) {
        stage_W(Ws, Wa, t);
        __syncthreads();
        mma_tile(Xs, Ws, ba, g_xnew, row0, N, t);
        __syncthreads();
        stage_W(Ws, Wd, t);
        __syncthreads();
        mma_tile(Xs, Ws, bd, g_Dx, row0, N, t);
    } else {
        int k = m - 1;
        stage_W(Ws, Wb + (size_t)k * DD * DD, t);
        __syncthreads();
        mma_tile(Xs, Ws, bb + k * DD, g_Bx + (size_t)k * N * DD, row0, N, t);
    }
}

// ---------------------------------------------------------------------------
// K5: agg v6 (r12 proven) — one warp per node, lane owns 2 dims (float2).
// ONE flat index chunk load covers all 3 k-segments; 4-unrolled gathers
// (MLP=4). BN stats fused.
// ---------------------------------------------------------------------------
__global__ __launch_bounds__(256) void agg_kernel(int N) {
    __shared__ float ssum[DD];
    __shared__ float ssq[DD];
    int t = threadIdx.x;
    if (t < DD) { ssum[t] = 0.f; ssq[t] = 0.f; }
    __syncthreads();

    int warp = (blockIdx.x * blockDim.x + t) >> 5;
    int lane = t & 31;

    if (warp < N) {
        int n = warp;
        int sv = 0;
        if (lane < 4) sv = __ldg(&g_segstart[3 * n + lane]);
        int s0 = __shfl_sync(0xffffffff, sv, 0);
        int s1 = __shfl_sync(0xffffffff, sv, 1);
        int s2 = __shfl_sync(0xffffffff, sv, 2);
        int s3 = __shfl_sync(0xffffffff, sv, 3);

        float2 d = *(const float2*)&g_Dx[(size_t)n * DD + lane * 2];

        int chunk = -1;
        int jv = 0;
        float eta0 = 0.f, eta1 = 0.f;

        #pragma unroll
        for (int k = 0; k < KK; k++) {
            int s = (k == 0) ? s0 : (k == 1) ? s1 : s2;
            int e = (k == 0) ? s1 : (k == 1) ? s2 : s3;
            const float* Bk = g_Bx + (size_t)k * N * DD + lane * 2;

            float num0 = 0.f, num1 = 0.f, den0 = 0.f, den1 = 0.f;

            int m = s;
            while (m < e) {
                int idx = m - s0;
                int c = idx >> 5;
                if (c != chunk) {
                    int li = min(s0 + (c << 5) + lane, s3 - 1);
                    jv = __ldg(&g_sorted[li]);
                    chunk = c;
                }
                int off = idx & 31;
                int avail = min(e - m, 32 - off);
                int q = 0;
                for (; q + 4 <= avail; q += 4) {
                    int j0 = __shfl_sync(0xffffffff, jv, off + q);
                    int j1 = __shfl_sync(0xffffffff, jv, off + q + 1);
                    int j2 = __shfl_sync(0xffffffff, jv, off + q + 2);
                    int j3 = __shfl_sync(0xffffffff, jv, off + q + 3);
                    float2 b0 = *(const float2*)(Bk + ((size_t)j0 << 6));
                    float2 b1 = *(const float2*)(Bk + ((size_t)j1 << 6));
                    float2 b2 = *(const float2*)(Bk + ((size_t)j2 << 6));
                    float2 b3 = *(const float2*)(Bk + ((size_t)j3 << 6));
                    float sa, sb;
                    sa = sigmoid_fast(d.x + b0.x); sb = sigmoid_fast(d.y + b0.y);
                    num0 += sa * b0.x; den0 += sa; num1 += sb * b0.y; den1 += sb;
                    sa = sigmoid_fast(d.x + b1.x); sb = sigmoid_fast(d.y + b1.y);
                    num0 += sa * b1.x; den0 += sa; num1 += sb * b1.y; den1 += sb;
                    sa = sigmoid_fast(d.x + b2.x); sb = sigmoid_fast(d.y + b2.y);
                    num0 += sa * b2.x; den0 += sa; num1 += sb * b2.y; den1 += sb;
                    sa = sigmoid_fast(d.x + b3.x); sb = sigmoid_fast(d.y + b3.y);
                    num0 += sa * b3.x; den0 += sa; num1 += sb * b3.y; den1 += sb;
                }
                for (; q < avail; q++) {
                    int j = __shfl_sync(0xffffffff, jv, off + q);
                    float2 b = *(const float2*)(Bk + ((size_t)j << 6));
                    float sa = sigmoid_fast(d.x + b.x);
                    float sb = sigmoid_fast(d.y + b.y);
                    num0 += sa * b.x; den0 += sa;
                    num1 += sb * b.y; den1 += sb;
                }
                m += avail;
            }
            eta0 += __fdividef(num0, den0 + AGG_EPS);
            eta1 += __fdividef(num1, den1 + AGG_EPS);
        }

        size_t obase = (size_t)n * DD + lane * 2;
        float2 a = *(const float2*)&g_xnew[obase];   // Ax
        float v0 = a.x + eta0 * (1.f / KK);
        float v1 = a.y + eta1 * (1.f / KK);
        float2 vo; vo.x = v0; vo.y = v1;
        *(float2*)&g_xnew[obase] = vo;

        atomicAdd(&ssum[lane * 2 + 0], v0);
        atomicAdd(&ssum[lane * 2 + 1], v1);
        atomicAdd(&ssq[lane * 2 + 0], v0 * v0);
        atomicAdd(&ssq[lane * 2 + 1], v1 * v1);
    }
    __syncthreads();
    if (t < DD) {
        atomicAdd(&g_fsum[t], ssum[t]);
        atomicAdd(&g_fsq[t],  ssq[t]);
    }
}

// ---------------------------------------------------------------------------
// K6: BatchNorm + ReLU (vectorized)
// ---------------------------------------------------------------------------
__global__ void bn_kernel(const float* __restrict__ gamma,
                          const float* __restrict__ beta,
                          float* __restrict__ out, int N) {
    int idx = blockIdx.x * blockDim.x + threadIdx.x;   // float4 index
    if (idx >= N * (DD / 4)) return;
    int d4 = (idx & 15) * 4;
    float invN = 1.f / (float)N;
    float4 x = *(const float4*)&g_xnew[(size_t)idx * 4];
    float4 o;
    #pragma unroll
    for (int i = 0; i < 4; i++) {
        int d = d4 + i;
        float mean = g_fsum[d] * invN;
        float var  = g_fsq[d] * invN - mean * mean;
        float xi = (i == 0) ? x.x : (i == 1) ? x.y : (i == 2) ? x.z : x.w;
        float y = gamma[d] * (xi - mean) * rsqrtf(var + BN_EPS) + beta[d];
        y = fmaxf(y, 0.f);
        if (i == 0) o.x = y; else if (i == 1) o.y = y; else if (i == 2) o.z = y; else o.w = y;
    }
    *(float4*)&out[(size_t)idx * 4] = o;
}

// ---------------------------------------------------------------------------
extern "C" void kernel_launch(void* const* d_in, const int* in_sizes, int n_in,
                              void* d_out, int out_size) {
    const float* xs    = (const float*)d_in[0];
    const int*   ei    = (const int*)d_in[1];
    const int*   ea    = (const int*)d_in[2];
    const float* Wa    = (const float*)d_in[3];
    const float* ba    = (const float*)d_in[4];
    const float* Wd    = (const float*)d_in[5];
    const float* bd    = (const float*)d_in[6];
    const float* Wb    = (const float*)d_in[7];
    const float* bb    = (const float*)d_in[8];
    const float* gamma = (const float*)d_in[9];
    const float* beta  = (const float*)d_in[10];
    float* out = (float*)d_out;

    int N = in_sizes[0] / (3 * DD);
    int E = in_sizes[2];
    int NK = N * KK;
    int nScanBlks = (NK + SCAN_BLK - 1) / SCAN_BLK;

    static cudaStream_t side = nullptr;
    static cudaEvent_t evFork = nullptr, evJoin = nullptr;
    static bool attrSet = false;
    if (!side) {
        cudaStreamCreateWithFlags(&side, cudaStreamNonBlocking);
        cudaEventCreateWithFlags(&evFork, cudaEventDisableTiming);
        cudaEventCreateWithFlags(&evJoin, cudaEventDisableTiming);
    }
    if (!attrSet) {
        cudaFuncSetAttribute(gemm_kernel,
                             cudaFuncAttributeMaxDynamicSharedMemorySize, GEMM_SMEM);
        attrSet = true;
    }

    cudaEventRecord(evFork, 0);
    cudaStreamWaitEvent(side, evFork, 0);

    zero_kernel<<<256, 256, 0, side>>>(NK);                       // #1
    hist_kernel<<<(E + 255) / 256, 256, 0, side>>>(ei, ea, E);    // #2
    scan1_kernel<<<nScanBlks, SCAN_BLK, 0, side>>>(NK);           // #3

    dim3 gGemm((N + GR - 1) / GR, 4);
    gemm_kernel<<<gGemm, 256, GEMM_SMEM>>>(xs, Wa, ba, Wd, bd, Wb, bb, N);  // #4 (profiled)

    scan23_kernel<<<(NK + 255) / 256, 256, 0, side>>>(NK, E, nScanBlks);    // #5
    scatter_kernel<<<(E + 255) / 256, 256, 0, side>>>(ei, ea, E);           // #6

    cudaEventRecord(evJoin, side);
    cudaStreamWaitEvent(0, evJoin, 0);

    agg_kernel<<<(N * 32 + 255) / 256, 256>>>(N);                 // #7

    bn_kernel<<<(N * (DD / 4) + 255) / 256, 256>>>(gamma, beta, out, N);    // #8
}